// round 6
// baseline (speedup 1.0000x reference)
#include <cuda_runtime.h>
#include <cstdint>

// KVGather: out[n,i,k,w,c] = r_weight[n,i,k] * kv[n, r_idx[n,i,k], w, c]
// N=16, P2=64, TOPK=8, W2=64, C_KV=512
// Effectively a pure 1.07 GiB write stream (kv reads are ~all L2 hits since
// kv ~fits in the 126 MB L2). Bound by achieved HBM write bandwidth.
// R6: persistent grid + batched 8-deep load window to maximize MLP.

#define KVG_N     16
#define KVG_P2    64
#define KVG_TOPK  8
#define KVG_W2    64
#define KVG_CKV   512

#define NUM_TILES   (KVG_N * KVG_P2 * KVG_TOPK)      // 8192
#define TILE_F4     (KVG_W2 * KVG_CKV / 4)           // 8192 float4 per tile
#define F4_PER_THR  8
#define THREADS     256
#define F4_PER_BLK  (F4_PER_THR * THREADS)           // 2048
#define NUM_CHUNKS  (NUM_TILES * (TILE_F4 / F4_PER_BLK))  // 32768
#define GRID_P      (148 * 8)                        // persistent: 8 blocks/SM

__global__ __launch_bounds__(THREADS)
void kvg_gather_kernel(const float4* __restrict__ kv,
                       const float*  __restrict__ r_weight,
                       const void*   __restrict__ r_idx,
                       float4*       __restrict__ out) {
    // ---- int64-vs-int32 index-width detection (once per block) ----
    // View r_idx as int32 words. int64 values in [0,64) -> every odd word 0.
    // int32 indices -> OR of 32 odd words nonzero w.p. 1-(1/64)^32.
    // Words [1..63] are in-bounds for both layouts; sectors are L2-hot.
    const int lane = threadIdx.x & 31;
    unsigned probe = ((const unsigned*)r_idx)[2 * lane + 1];
    const bool is64 = (__reduce_or_sync(0xffffffffu, probe) == 0u);

    for (int c = blockIdx.x; c < NUM_CHUNKS; c += GRID_P) {
        const int tile  = c >> 2;           // 4 chunks per tile
        const int chunk = c & 3;
        const int n     = tile >> 9;        // / (P2*TOPK)

        long long idx;
        if (is64) idx = ((const long long*)r_idx)[tile];
        else      idx = (long long)((const int*)r_idx)[tile];
        const float wt = r_weight[tile];

        const float4* __restrict__ src =
            kv + ((long long)n * KVG_P2 + idx) * (long long)TILE_F4;
        float4* __restrict__ dst = out + (long long)tile * (long long)TILE_F4;

        const int base = chunk * F4_PER_BLK + threadIdx.x;

        // Batched: issue all 8 loads first (deep MLP), then 8 scaled
        // streaming stores. ~56 regs; occupancy stays ample for BW.
        float4 r[F4_PER_THR];
#pragma unroll
        for (int j = 0; j < F4_PER_THR; j++)
            r[j] = __ldg(&src[base + j * THREADS]);

#pragma unroll
        for (int j = 0; j < F4_PER_THR; j++) {
            float4 v = r[j];
            v.x *= wt; v.y *= wt; v.z *= wt; v.w *= wt;
            __stcs(&dst[base + j * THREADS], v);
        }
    }
}

extern "C" void kernel_launch(void* const* d_in, const int* in_sizes, int n_in,
                              void* d_out, int out_size) {
    // metadata order: r_idx, r_weight, kv
    const void*  r_idx    = d_in[0];
    const float* r_weight = (const float*)d_in[1];
    const float4* kv      = (const float4*)d_in[2];
    float4* out           = (float4*)d_out;

    kvg_gather_kernel<<<GRID_P, THREADS>>>(kv, r_weight, r_idx, out);
}

// round 7
// speedup vs baseline: 1.4187x; 1.4187x over previous
#include <cuda_runtime.h>
#include <cstdint>

// KVGather: out[n,i,k,w,c] = r_weight[n,i,k] * kv[n, r_idx[n,i,k], w, c]
// N=16, P2=64, TOPK=8, W2=64, C_KV=512
// Effectively a 1.07 GiB compulsory write stream + ~75 MB L2-spill reads;
// pinned at 6567 GB/s (82.8% DRAM) in R1/R5. R7 A/B: default-policy stores
// instead of __stcs — let L2 batch full-line writebacks to the DRAM
// controllers instead of eager evict-first bursts.

#define KVG_N     16
#define KVG_P2    64
#define KVG_TOPK  8
#define KVG_W2    64
#define KVG_CKV   512

#define NUM_TILES   (KVG_N * KVG_P2 * KVG_TOPK)      // 8192
#define TILE_F4     (KVG_W2 * KVG_CKV / 4)           // 8192 float4 per tile (128 KB)
#define F4_PER_THR  8
#define THREADS     256
#define F4_PER_BLK  (F4_PER_THR * THREADS)           // 2048
#define BLKS_PER_TILE (TILE_F4 / F4_PER_BLK)         // 4
#define GRID        (NUM_TILES * BLKS_PER_TILE)      // 32768

__global__ __launch_bounds__(THREADS, 8)
void kvg_gather_kernel(const float4* __restrict__ kv,
                       const float*  __restrict__ r_weight,
                       const void*   __restrict__ r_idx,
                       float4*       __restrict__ out) {
    const int bid   = blockIdx.x;
    const int tile  = bid >> 2;            // BLKS_PER_TILE = 4
    const int chunk = bid & 3;
    const int n     = tile >> 9;           // / (P2*TOPK)

    // ---- int64-vs-int32 index-width detection, fused in-kernel ----
    // View r_idx as int32 words. int64 values in [0,64) -> every odd word 0.
    // int32 indices -> OR of 32 odd words nonzero w.p. 1-(1/64)^32.
    // Words [1..63] are in-bounds for both layouts; sectors are L2-hot.
    const int lane = threadIdx.x & 31;
    unsigned probe = ((const unsigned*)r_idx)[2 * lane + 1];
    unsigned odd_or = __reduce_or_sync(0xffffffffu, probe);
    const bool is64 = (odd_or == 0u);

    long long idx;
    if (is64) idx = ((const long long*)r_idx)[tile];
    else      idx = (long long)((const int*)r_idx)[tile];

    const float wt = r_weight[tile];

    const float4* __restrict__ src =
        kv + ((long long)n * KVG_P2 + idx) * (long long)TILE_F4;
    float4* __restrict__ dst = out + (long long)tile * (long long)TILE_F4;

    const int base = chunk * F4_PER_BLK + threadIdx.x;

#pragma unroll
    for (int j = 0; j < F4_PER_THR; j++) {
        const int p = base + j * THREADS;
        float4 v = __ldg(&src[p]);
        v.x *= wt; v.y *= wt; v.z *= wt; v.w *= wt;
        // Default-policy store (A/B vs __stcs): allow L2 to accumulate and
        // batch full-line writebacks to DRAM.
        dst[p] = v;
    }
}

extern "C" void kernel_launch(void* const* d_in, const int* in_sizes, int n_in,
                              void* d_out, int out_size) {
    // metadata order: r_idx, r_weight, kv
    const void*  r_idx    = d_in[0];
    const float* r_weight = (const float*)d_in[1];
    const float4* kv      = (const float4*)d_in[2];
    float4* out           = (float4*)d_out;

    kvg_gather_kernel<<<GRID, THREADS>>>(kv, r_weight, r_idx, out);
}

// round 8
// speedup vs baseline: 1.4543x; 1.0251x over previous
#include <cuda_runtime.h>
#include <cstdint>

// KVGather: out[n,i,k,w,c] = r_weight[n,i,k] * kv[n, r_idx[n,i,k], w, c]
// N=16, P2=64, TOPK=8, W2=64, C_KV=512
// 1.074 GiB compulsory write + ~75 MB kv read spill (kv ~fits in 126 MB L2).
// R5 path proven best: 128-bit nc loads + __stcs stores @ 6567 GB/s.
// R8: single change — pin kv reads in L2 via createpolicy evict_last +
// ld.global.nc.L2::cache_hint (legal at 128-bit, unlike the direct modifier).

#define KVG_N     16
#define KVG_P2    64
#define KVG_TOPK  8
#define KVG_W2    64
#define KVG_CKV   512

#define NUM_TILES   (KVG_N * KVG_P2 * KVG_TOPK)      // 8192
#define TILE_F4     (KVG_W2 * KVG_CKV / 4)           // 8192 float4 per tile (128 KB)
#define F4_PER_THR  8
#define THREADS     256
#define F4_PER_BLK  (F4_PER_THR * THREADS)           // 2048
#define BLKS_PER_TILE (TILE_F4 / F4_PER_BLK)         // 4
#define GRID        (NUM_TILES * BLKS_PER_TILE)      // 32768

__device__ __forceinline__ float4 ldg_l2el(const float4* p, uint64_t pol) {
    float4 v;
    asm("ld.global.nc.L2::cache_hint.v4.f32 {%0,%1,%2,%3}, [%4], %5;"
        : "=f"(v.x), "=f"(v.y), "=f"(v.z), "=f"(v.w)
        : "l"(p), "l"(pol));
    return v;
}

__global__ __launch_bounds__(THREADS, 8)
void kvg_gather_kernel(const float4* __restrict__ kv,
                       const float*  __restrict__ r_weight,
                       const void*   __restrict__ r_idx,
                       float4*       __restrict__ out) {
    const int bid   = blockIdx.x;
    const int tile  = bid >> 2;            // BLKS_PER_TILE = 4
    const int chunk = bid & 3;
    const int n     = tile >> 9;           // / (P2*TOPK)

    // ---- int64-vs-int32 index-width detection, fused in-kernel ----
    // View r_idx as int32 words. int64 values in [0,64) -> every odd word 0.
    // int32 indices -> OR of 32 odd words nonzero w.p. 1-(1/64)^32.
    // Words [1..63] are in-bounds for both layouts; sectors are L2-hot.
    const int lane = threadIdx.x & 31;
    unsigned probe = ((const unsigned*)r_idx)[2 * lane + 1];
    unsigned odd_or = __reduce_or_sync(0xffffffffu, probe);
    const bool is64 = (odd_or == 0u);

    long long idx;
    if (is64) idx = ((const long long*)r_idx)[tile];
    else      idx = (long long)((const int*)r_idx)[tile];

    const float wt = r_weight[tile];

    // L2 evict-last policy for the hot kv read set (fraction 1.0).
    uint64_t pol;
    asm("createpolicy.fractional.L2::evict_last.b64 %0, 1.0;" : "=l"(pol));

    const float4* __restrict__ src =
        kv + ((long long)n * KVG_P2 + idx) * (long long)TILE_F4;
    float4* __restrict__ dst = out + (long long)tile * (long long)TILE_F4;

    const int base = chunk * F4_PER_BLK + threadIdx.x;

#pragma unroll
    for (int j = 0; j < F4_PER_THR; j++) {
        const int p = base + j * THREADS;
        float4 v = ldg_l2el(&src[p], pol);
        v.x *= wt; v.y *= wt; v.z *= wt; v.w *= wt;
        // Streaming store (proven in R7 A/B): evict-first write stream.
        __stcs(&dst[p], v);
    }
}

extern "C" void kernel_launch(void* const* d_in, const int* in_sizes, int n_in,
                              void* d_out, int out_size) {
    // metadata order: r_idx, r_weight, kv
    const void*  r_idx    = d_in[0];
    const float* r_weight = (const float*)d_in[1];
    const float4* kv      = (const float4*)d_in[2];
    float4* out           = (float4*)d_out;

    kvg_gather_kernel<<<GRID, THREADS>>>(kv, r_weight, r_idx, out);
}